// round 6
// baseline (speedup 1.0000x reference)
#include <cuda_runtime.h>
#include <math.h>

#define BB 32
#define TT 256
#define EE 256
#define HH 512
#define G4 2048   // 4*HH
#define KK 20
#define START_TAG 18
#define END_TAG 19
#define NEGV (-10000.0f)
#define NBLK_DIR 64   // blocks per direction in k_lstm

// ---------------- device-global scratch ----------------
__device__ float g_pre[(size_t)2 * TT * G4 * BB];        // [dir][t][gate][b]
__device__ float g_h[2][2][HH * BB];                     // [dir][buf][j][b]
__device__ float g_lo2[(size_t)2 * TT * HH * BB];        // [dir][t][j][b]
__device__ float g_feats[(size_t)BB * TT * KK];          // [b][t][k]
__device__ unsigned g_arrive[2];
__device__ unsigned g_release[2];

// ---------------- helpers ----------------
__device__ __forceinline__ unsigned smem_u32(const void* p) {
    unsigned a;
    asm("{ .reg .u64 t; cvta.to.shared.u64 t, %1; cvt.u32.u64 %0, t; }" : "=r"(a) : "l"(p));
    return a;
}
__device__ __forceinline__ void fma2(unsigned long long& acc, unsigned long long a, unsigned long long b) {
    asm("fma.rn.f32x2 %0, %1, %2, %0;" : "+l"(acc) : "l"(a), "l"(b));
}
__device__ __forceinline__ void lds_v2u64(unsigned addr, unsigned long long& a, unsigned long long& b) {
    asm("ld.shared.v2.u64 {%0,%1}, [%2];" : "=l"(a), "=l"(b) : "r"(addr));
}
__device__ __forceinline__ unsigned long long lds_u64(unsigned addr) {
    unsigned long long v;
    asm("ld.shared.u64 %0, [%1];" : "=l"(v) : "r"(addr));
    return v;
}
__device__ __forceinline__ void sts_u64(unsigned addr, unsigned long long v) {
    asm volatile("st.shared.u64 [%0], %1;" :: "r"(addr), "l"(v));
}
__device__ __forceinline__ float hsum2(unsigned long long a) {
    return __uint_as_float((unsigned)a) + __uint_as_float((unsigned)(a >> 32));
}

// ---------------- init: reset barrier state ----------------
__global__ void k_init() {
    if (threadIdx.x < 2) { g_arrive[threadIdx.x] = 0u; g_release[threadIdx.x] = 0u; }
}

// ---------------- input-projection GEMM (f32x2), embedding gather fused ----------------
__global__ void __launch_bounds__(256) k_pregemm(
    const int* __restrict__ sent, const float* __restrict__ emb,
    const float* __restrict__ Wf, const float* __restrict__ Wb,
    const float* __restrict__ bf, const float* __restrict__ bb)
{
    extern __shared__ float sm[];
    float* xsf = sm;               // x pairs: [ep][b][2], stride 68 floats/ep
    float* wsf = sm + 128 * 68;    // w rows:  [r][e], stride 258 floats/row
    __shared__ int stok[BB];

    int t = blockIdx.x, gc = blockIdx.y, dir = blockIdx.z;
    int tid = threadIdx.x;
    if (tid < BB) stok[tid] = sent[tid * TT + t];
    __syncthreads();

    const float* W  = dir ? Wb : Wf;
    const float* bi = dir ? bb : bf;

    for (int i = tid; i < BB * EE; i += 256) {
        int b = i >> 8, e = i & 255;
        xsf[(e >> 1) * 68 + b * 2 + (e & 1)] = emb[(size_t)stok[b] * EE + e];
    }
    int g0blk = gc * 64;
    for (int i = tid; i < 64 * EE; i += 256) {
        int r = i >> 8, e = i & 255;
        wsf[r * 258 + e] = W[(size_t)(g0blk + r) * EE + e];
    }
    __syncthreads();

    int tx = tid & 15, ty = tid >> 4;
    int b0 = tx * 2;
    int g0 = ty * 4;
    unsigned xb = smem_u32(xsf) + (unsigned)b0 * 8u;
    unsigned wb = smem_u32(wsf) + (unsigned)g0 * 1032u;

    unsigned long long a[4][2];
#pragma unroll
    for (int q = 0; q < 4; q++) { a[q][0] = 0ull; a[q][1] = 0ull; }

#pragma unroll 4
    for (int ep = 0; ep < 128; ep++) {
        unsigned long long x0, x1;
        lds_v2u64(xb + (unsigned)ep * 272u, x0, x1);
        unsigned long long w0 = lds_u64(wb + (unsigned)ep * 8u);
        unsigned long long w1 = lds_u64(wb + 1032u + (unsigned)ep * 8u);
        unsigned long long w2 = lds_u64(wb + 2064u + (unsigned)ep * 8u);
        unsigned long long w3 = lds_u64(wb + 3096u + (unsigned)ep * 8u);
        fma2(a[0][0], w0, x0); fma2(a[0][1], w0, x1);
        fma2(a[1][0], w1, x0); fma2(a[1][1], w1, x1);
        fma2(a[2][0], w2, x0); fma2(a[2][1], w2, x1);
        fma2(a[3][0], w3, x0); fma2(a[3][1], w3, x1);
    }

    size_t base = (((size_t)dir * TT + t) * G4 + g0blk) * BB;
#pragma unroll
    for (int q = 0; q < 4; q++) {
        int g = g0 + q;
        float bv = bi[g0blk + g];
        float2 st = make_float2(hsum2(a[q][0]) + bv, hsum2(a[q][1]) + bv);
        *(float2*)&g_pre[base + (size_t)g * BB + b0] = st;
    }
}

// ---------------- persistent BiLSTM recurrence, dir-specialized ----------------
// 128 blocks: dir = bx>>6, jgrp = bx&63 -> j in [jgrp*8, jgrp*8+8).
// 32 rows per block (row = j_loc*4 + gate). Warp w: rg = w&3 (row-group of 8 = j-pair,
// all gates), kh = w>>2 (k-half). Lane: r2 = lane>>3 (row-pair), o = lane&7 (b-quad).
// smem: w-dup [kh][rg][k 256][riw 8][dup 2] 128KB; h [k 512][b 32] 64KB; part 8KB.
__global__ void __launch_bounds__(256, 1) k_lstm(
    const float* __restrict__ Wfhh, const float* __restrict__ Wbhh,
    const float* __restrict__ bfhh, const float* __restrict__ bbhh,
    const int* __restrict__ lengths)
{
    extern __shared__ float sm[];
    float* swd  = sm;               // 32768 floats
    float* sh   = sm + 32768;       // 16384 floats
    float* part = sm + 49152;       // 2048 floats: [kh][j_loc][gate][b]

    const int bx = (int)blockIdx.x;
    const int dir = bx >> 6, jgrp = bx & 63;
    const int tid = threadIdx.x;
    const int w = tid >> 5, lane = tid & 31;
    const int rg = w & 3, kh = w >> 2;
    const int r2 = lane >> 3, o = lane & 7;
    const int j_loc = tid >> 5;          // finalize role: tid = j_loc*32 + b ... careful:
    const int fb = tid & 31;             // finalize batch
    const int fj = tid >> 5;             // finalize j_loc (0..7)
    const float* __restrict__ Whh = dir ? Wbhh : Wfhh;
    const float* __restrict__ bhh = dir ? bbhh : bfhh;

    // ---- one-time weight load (duplicated pairs) ----
    // swd[((kh*4+rg)*256+k)*16 + riw*2 + dup] = Whh[(gate*HH + jgrp*8 + rg*2 + (riw>>2))*HH + kh*256 + k]
    for (int idx = tid; idx < 32768; idx += 256) {
        int riw = (idx >> 1) & 7;
        int k   = (idx >> 4) & 255;
        int rgx = (idx >> 12) & 3;
        int khx = idx >> 14;
        int gate = riw & 3;
        int jl   = rgx * 2 + (riw >> 2);
        swd[idx] = Whh[((size_t)(gate * HH + jgrp * 8 + jl)) * HH + khx * 256 + k];
    }
    for (int i = tid; i < HH * BB; i += 256) sh[i] = 0.0f;

    float bias[4];
#pragma unroll
    for (int g = 0; g < 4; g++) bias[g] = bhh[g * HH + jgrp * 8 + fj];
    const int mylen = lengths[fb];
    const int jglob = jgrp * 8 + fj;

    const unsigned wbase = smem_u32(swd) + ((unsigned)(kh * 4 + rg) * 256u) * 64u + (unsigned)r2 * 16u;
    const unsigned hbase = smem_u32(sh) + (unsigned)kh * 256u * 128u + (unsigned)o * 16u;
    const unsigned pbase = smem_u32(part);
    __syncthreads();

    // prefetch pre-gates for t=0 (own (j, gate, b))
    float cz[4];
    int cpos = (dir && 0 < mylen) ? (mylen - 1) : 0;
    {
        size_t pb = (((size_t)dir * TT + cpos) * G4) * BB + fb;
#pragma unroll
        for (int g = 0; g < 4; g++) cz[g] = __ldcs(&g_pre[pb + (size_t)(g * HH + jglob) * BB]);
    }

    float c = 0.0f;
    for (int t = 0; t < TT; t++) {
        // prefetch next-step pre-gates
        float nz[4] = {0.f, 0.f, 0.f, 0.f};
        int npos = 0;
        if (t + 1 < TT) {
            npos = t + 1;
            if (dir && (t + 1) < mylen) npos = mylen - 1 - (t + 1);
            size_t pb = (((size_t)dir * TT + npos) * G4) * BB + fb;
#pragma unroll
            for (int g = 0; g < 4; g++) nz[g] = __ldcs(&g_pre[pb + (size_t)(g * HH + jglob) * BB]);
        }

        if (t) {
            if (tid == 0) {
                unsigned r;
                do {
                    asm volatile("ld.acquire.gpu.global.u32 %0, [%1];"
                                 : "=r"(r) : "l"(&g_release[dir]) : "memory");
                } while (r < (unsigned)t);
            }
            __syncthreads();
            // copy h[t] (64KB) from L2 into smem [k][b]
            const float4* src = (const float4*)&g_h[dir][t & 1][0];
            float4* dst = (float4*)sh;
#pragma unroll
            for (int q = 0; q < 16; q++) dst[tid + q * 256] = __ldcg(&src[tid + q * 256]);
            __syncthreads();
        }

        // ---- MAC: warp (rg,kh), lane (r2,o): 2 rows x 4 b over 256 k ----
        unsigned long long a00 = 0, a01 = 0, a10 = 0, a11 = 0;  // [row][bpair]
#pragma unroll 8
        for (int k = 0; k < 256; k++) {
            unsigned long long w0, w1;   // (w_r0,w_r0),(w_r1,w_r1)
            lds_v2u64(wbase + (unsigned)k * 64u, w0, w1);
            unsigned long long h0, h1;   // (h_b0,h_b1),(h_b2,h_b3)
            lds_v2u64(hbase + (unsigned)k * 128u, h0, h1);
            fma2(a00, w0, h0); fma2(a01, w0, h1);
            fma2(a10, w1, h0); fma2(a11, w1, h1);
        }

        // store partials: part[kh][j_loc][gate][b]
        {
            int riw0 = r2 * 2 + 0, riw1 = r2 * 2 + 1;
            int jl0 = rg * 2 + (riw0 >> 2), g0 = riw0 & 3;
            int jl1 = rg * 2 + (riw1 >> 2), g1 = riw1 & 3;
            unsigned p0 = pbase + (((unsigned)(kh * 8 + jl0) * 4 + (unsigned)g0) * 32 + (unsigned)o * 4) * 4u;
            unsigned p1 = pbase + (((unsigned)(kh * 8 + jl1) * 4 + (unsigned)g1) * 32 + (unsigned)o * 4) * 4u;
            sts_u64(p0, a00); sts_u64(p0 + 8u, a01);
            sts_u64(p1, a10); sts_u64(p1 + 8u, a11);
        }
        __syncthreads();

        // ---- finalize: thread (fj, fb) ----
        float z[4];
#pragma unroll
        for (int g = 0; g < 4; g++) {
            z[g] = cz[g] + bias[g]
                 + part[((0 * 8 + fj) * 4 + g) * 32 + fb]
                 + part[((1 * 8 + fj) * 4 + g) * 32 + fb];
        }

        float gi = 1.0f / (1.0f + expf(-z[0]));
        float gf = 1.0f / (1.0f + expf(-z[1]));
        float gg = 1.0f - 2.0f / (expf(2.0f * z[2]) + 1.0f);
        float go = 1.0f / (1.0f + expf(-z[3]));

        c = gf * c + gi * gg;
        float h = go * (1.0f - 2.0f / (expf(2.0f * c) + 1.0f));

        g_h[dir][(t + 1) & 1][jglob * BB + fb] = h;
        g_lo2[(((size_t)dir * TT + cpos) * HH + jglob) * BB + fb] = h;

        if (t + 1 < TT) {
            __syncthreads();    // all h stores issued
            if (tid == 0) {
                unsigned old;
                asm volatile("atom.release.gpu.global.add.u32 %0, [%1], %2;"
                             : "=r"(old) : "l"(&g_arrive[dir]), "r"(1u) : "memory");
                if (old == (unsigned)(NBLK_DIR * (t + 1) - 1)) {
                    asm volatile("st.release.gpu.global.u32 [%0], %1;"
                                 :: "l"(&g_release[dir]), "r"((unsigned)(t + 1)) : "memory");
                }
            }
        } else {
            __syncthreads();
        }
#pragma unroll
        for (int g = 0; g < 4; g++) cz[g] = nz[g];
        cpos = npos;
    }
}

// ---------------- feats: per-t GEMM  out[k][b] = Wout[k][:] . h[:][b] ----------------
__global__ void __launch_bounds__(640) k_feats(
    const float* __restrict__ Wout, const float* __restrict__ bout)
{
    extern __shared__ float sm[];
    float* sW = sm;                 // [20][1024]
    float* sh = sm + 20480;         // [1024][32]
    __shared__ float sb[KK];
    int t = blockIdx.x;
    int tid = threadIdx.x, warp = tid >> 5, lane = tid & 31;

    for (int i = tid * 4; i < KK * 2 * HH; i += 2560)
        *(float4*)&sW[i] = *(const float4*)&Wout[i];
    for (int d = 0; d < 2; d++) {
        const float4* src = (const float4*)&g_lo2[(((size_t)d * TT + t) * HH) * BB];
        float4* dst = (float4*)&sh[d * HH * BB];
        for (int i = tid; i < HH * BB / 4; i += 640) dst[i] = src[i];
    }
    if (tid < KK) sb[tid] = bout[tid];
    __syncthreads();

    float acc = 0.0f;
    const float* wrow = &sW[warp * 2 * HH];
#pragma unroll 8
    for (int jj = 0; jj < 2 * HH; jj += 4) {
        float4 wv = *(const float4*)&wrow[jj];
        acc = fmaf(wv.x, sh[(jj + 0) * BB + lane], acc);
        acc = fmaf(wv.y, sh[(jj + 1) * BB + lane], acc);
        acc = fmaf(wv.z, sh[(jj + 2) * BB + lane], acc);
        acc = fmaf(wv.w, sh[(jj + 3) * BB + lane], acc);
    }
    g_feats[((size_t)lane * TT + t) * KK + warp] = acc + sb[warp];
}

// ---------------- Viterbi forward + backtrace, one warp per batch ----------------
__global__ void k_viterbi(const float* __restrict__ trans,
                          const int* __restrict__ lengths,
                          float* __restrict__ out)
{
    __shared__ unsigned char bp[TT][KK];
    int b = blockIdx.x;
    int nx = threadIdx.x;
    int len = lengths[b];

    float tr[KK];
#pragma unroll
    for (int p = 0; p < KK; p++) tr[p] = (nx < KK) ? trans[nx * KK + p] : 0.0f;

    float fv = (nx == START_TAG) ? 0.0f : NEGV;
    for (int t = 0; t < len; t++) {
        float best = -INFINITY; int barg = 0;
#pragma unroll
        for (int p = 0; p < KK; p++) {
            float fvp = __shfl_sync(0xffffffffu, fv, p);
            float s = fvp + tr[p];
            if (s > best) { best = s; barg = p; }
        }
        if (nx < KK) {
            bp[t][nx] = (unsigned char)barg;
            fv = best + g_feats[((size_t)b * TT + t) * KK + nx];
        } else {
            fv = NEGV;
        }
        __syncwarp();
    }

    float term = (nx < KK) ? (fv + trans[END_TAG * KK + nx]) : -INFINITY;
    float bestv = -INFINITY; int bt = 0;
#pragma unroll
    for (int p = 0; p < KK; p++) {
        float v = __shfl_sync(0xffffffffu, term, p);
        if (v > bestv) { bestv = v; bt = p; }
    }

    if (nx == 0) {
        out[b] = bestv;
        float* path = out + BB + (size_t)b * (TT + 1);
        path[TT] = (float)bt;
        int cur = bt;
        for (int i = 1; i <= len; i++) {
            cur = bp[len - i][cur];
            path[TT - i] = (float)cur;
        }
        for (int idx = 0; idx < TT - len; idx++) path[idx] = (float)KK;
    }
}

// ---------------- launch ----------------
extern "C" void kernel_launch(void* const* d_in, const int* in_sizes, int n_in,
                              void* d_out, int out_size) {
    const int*   sent  = (const int*)d_in[0];
    const int*   lens  = (const int*)d_in[1];
    const float* emb   = (const float*)d_in[2];
    const float* Wf_ih = (const float*)d_in[3];
    const float* Wf_hh = (const float*)d_in[4];
    const float* bf_ih = (const float*)d_in[5];
    const float* bf_hh = (const float*)d_in[6];
    const float* Wb_ih = (const float*)d_in[7];
    const float* Wb_hh = (const float*)d_in[8];
    const float* bb_ih = (const float*)d_in[9];
    const float* bb_hh = (const float*)d_in[10];
    const float* Wout  = (const float*)d_in[11];
    const float* bout  = (const float*)d_in[12];
    const float* trans = (const float*)d_in[13];
    float* out = (float*)d_out;

    const int smem_pregemm = (128 * 68 + 64 * 258) * 4;          // ~98.5 KB
    const int smem_lstm    = (32768 + 16384 + 2048) * 4;         // 200.7 KB
    const int smem_feats   = (KK * 2 * HH + 2 * HH * BB) * 4;    // 208 KB
    cudaFuncSetAttribute(k_pregemm, cudaFuncAttributeMaxDynamicSharedMemorySize, smem_pregemm);
    cudaFuncSetAttribute(k_lstm,    cudaFuncAttributeMaxDynamicSharedMemorySize, smem_lstm);
    cudaFuncSetAttribute(k_feats,   cudaFuncAttributeMaxDynamicSharedMemorySize, smem_feats);

    k_init<<<1, 32>>>();

    k_pregemm<<<dim3(TT, G4 / 64, 2), 256, smem_pregemm>>>(sent, emb, Wf_ih, Wb_ih, bf_ih, bb_ih);

    k_lstm<<<2 * NBLK_DIR, 256, smem_lstm>>>(Wf_hh, Wb_hh, bf_hh, bb_hh, lens);

    k_feats<<<TT, 640, smem_feats>>>(Wout, bout);

    k_viterbi<<<BB, 32>>>(trans, lens, out);
}

// round 7
// speedup vs baseline: 1.0510x; 1.0510x over previous
#include <cuda_runtime.h>
#include <math.h>

#define BB 32
#define TT 256
#define EE 256
#define HH 512
#define G4 2048   // 4*HH
#define KK 20
#define START_TAG 18
#define END_TAG 19
#define NEGV (-10000.0f)
#define NBLK 128   // k_lstm blocks; each handles 4 fwd j + 4 bwd j

// ---------------- device-global scratch ----------------
__device__ float g_pre[(size_t)2 * TT * G4 * BB];        // [dir][t][gate][b]
__device__ float g_h[2][2][HH * BB];                     // [dir][buf][j][b]
__device__ float g_lo2[(size_t)2 * TT * HH * BB];        // [dir][t][j][b]
__device__ float g_feats[(size_t)BB * TT * KK];          // [b][t][k]
__device__ unsigned g_arr1[2][8];                        // level-1 arrive counters
__device__ unsigned g_arr2[2];                           // root counters
__device__ unsigned g_release[2];

// ---------------- helpers ----------------
__device__ __forceinline__ unsigned smem_u32(const void* p) {
    unsigned a;
    asm("{ .reg .u64 t; cvta.to.shared.u64 t, %1; cvt.u32.u64 %0, t; }" : "=r"(a) : "l"(p));
    return a;
}
__device__ __forceinline__ void fma2(unsigned long long& acc, unsigned long long a, unsigned long long b) {
    asm("fma.rn.f32x2 %0, %1, %2, %0;" : "+l"(acc) : "l"(a), "l"(b));
}
__device__ __forceinline__ void lds_v2u64(unsigned addr, unsigned long long& a, unsigned long long& b) {
    asm("ld.shared.v2.u64 {%0,%1}, [%2];" : "=l"(a), "=l"(b) : "r"(addr));
}
__device__ __forceinline__ unsigned long long lds_u64(unsigned addr) {
    unsigned long long v;
    asm("ld.shared.u64 %0, [%1];" : "=l"(v) : "r"(addr));
    return v;
}
__device__ __forceinline__ void sts_v2u64(unsigned addr, unsigned long long a, unsigned long long b) {
    asm volatile("st.shared.v2.u64 [%0], {%1,%2};" :: "r"(addr), "l"(a), "l"(b));
}
__device__ __forceinline__ unsigned long long pack2(unsigned x) {
    unsigned long long v;
    asm("mov.b64 %0, {%1,%1};" : "=l"(v) : "r"(x));
    return v;
}
__device__ __forceinline__ float hsum2(unsigned long long a) {
    return __uint_as_float((unsigned)a) + __uint_as_float((unsigned)(a >> 32));
}
__device__ __forceinline__ void named_bar(int id) {
    asm volatile("bar.sync %0, 128;" :: "r"(id) : "memory");
}

// ---------------- init: reset barrier state (inside graph, every replay) ----------------
__global__ void k_init() {
    if (threadIdx.x < 16) g_arr1[threadIdx.x >> 3][threadIdx.x & 7] = 0u;
    if (threadIdx.x < 2) { g_arr2[threadIdx.x] = 0u; g_release[threadIdx.x] = 0u; }
}

// no-op: shifts launch order so ncu -s 5 profiles k_lstm
__global__ void k_nop() {}

// ---------------- input-projection GEMM (f32x2), embedding gather fused ----------------
__global__ void __launch_bounds__(256) k_pregemm(
    const int* __restrict__ sent, const float* __restrict__ emb,
    const float* __restrict__ Wf, const float* __restrict__ Wb,
    const float* __restrict__ bf, const float* __restrict__ bb)
{
    extern __shared__ float sm[];
    float* xsf = sm;               // x pairs: [ep][b][2], stride 68 floats/ep
    float* wsf = sm + 128 * 68;    // w rows:  [r][e], stride 258 floats/row
    __shared__ int stok[BB];

    int t = blockIdx.x, gc = blockIdx.y, dir = blockIdx.z;
    int tid = threadIdx.x;
    if (tid < BB) stok[tid] = sent[tid * TT + t];
    __syncthreads();

    const float* W  = dir ? Wb : Wf;
    const float* bi = dir ? bb : bf;

    for (int i = tid; i < BB * EE; i += 256) {
        int b = i >> 8, e = i & 255;
        xsf[(e >> 1) * 68 + b * 2 + (e & 1)] = emb[(size_t)stok[b] * EE + e];
    }
    int g0blk = gc * 64;
    for (int i = tid; i < 64 * EE; i += 256) {
        int r = i >> 8, e = i & 255;
        wsf[r * 258 + e] = W[(size_t)(g0blk + r) * EE + e];
    }
    __syncthreads();

    int tx = tid & 15, ty = tid >> 4;
    int b0 = tx * 2;
    int g0 = ty * 4;
    unsigned xb = smem_u32(xsf) + (unsigned)b0 * 8u;
    unsigned wb = smem_u32(wsf) + (unsigned)g0 * 1032u;

    unsigned long long a[4][2];
#pragma unroll
    for (int q = 0; q < 4; q++) { a[q][0] = 0ull; a[q][1] = 0ull; }

#pragma unroll 4
    for (int ep = 0; ep < 128; ep++) {
        unsigned long long x0, x1;
        lds_v2u64(xb + (unsigned)ep * 272u, x0, x1);
        unsigned long long w0 = lds_u64(wb + (unsigned)ep * 8u);
        unsigned long long w1 = lds_u64(wb + 1032u + (unsigned)ep * 8u);
        unsigned long long w2 = lds_u64(wb + 2064u + (unsigned)ep * 8u);
        unsigned long long w3 = lds_u64(wb + 3096u + (unsigned)ep * 8u);
        fma2(a[0][0], w0, x0); fma2(a[0][1], w0, x1);
        fma2(a[1][0], w1, x0); fma2(a[1][1], w1, x1);
        fma2(a[2][0], w2, x0); fma2(a[2][1], w2, x1);
        fma2(a[3][0], w3, x0); fma2(a[3][1], w3, x1);
    }

    size_t base = (((size_t)dir * TT + t) * G4 + g0blk) * BB;
#pragma unroll
    for (int q = 0; q < 4; q++) {
        int g = g0 + q;
        float bv = bi[g0blk + g];
        float2 st = make_float2(hsum2(a[q][0]) + bv, hsum2(a[q][1]) + bv);
        *(float2*)&g_pre[base + (size_t)g * BB + b0] = st;
    }
}

// ---------------- persistent BiLSTM recurrence, fused dirs, k-split warps ----------------
// 128 blocks x 256 threads. Block owns j in [jgrp*4, jgrp*4+4) for BOTH dirs.
// Warp w: dir = w>>2, kq = w&3 (k-quarter of 128). Lane: r2 = lane>>2 (row-pair of the
// half's 16 rows = 4j x 4gates), o = lane&3 (b-quad; each lane covers 8 b via 2 loads).
// smem floats: sW [2][512][16] @0; sh [2][512][32] @16384; part [2][4][16][32] @49152.
__global__ void __launch_bounds__(256, 1) k_lstm(
    const float* __restrict__ Wfhh, const float* __restrict__ Wbhh,
    const float* __restrict__ bfhh, const float* __restrict__ bbhh,
    const int* __restrict__ lengths)
{
    extern __shared__ float sm[];
    const int jgrp = (int)blockIdx.x;
    const int tid = threadIdx.x;
    const int w = tid >> 5, lane = tid & 31;
    const int dir = w >> 2, kq = w & 3;
    const int r2 = lane >> 2, o = lane & 3;
    const int ht = tid & 127;
    const int fj = ht >> 5;     // finalize j_loc 0..3
    const int fb = ht & 31;     // finalize batch
    const float* __restrict__ bhh = dir ? bbhh : bfhh;

    // one-time weight load: sW[half][k][row], row = gate*4 + jl
    for (int idx = tid; idx < 16384; idx += 256) {
        int half = idx >> 13;
        int r = idx & 8191;
        int k = r >> 4, row = r & 15;
        int gate = row >> 2, jl = row & 3;
        const float* W = half ? Wbhh : Wfhh;
        sm[idx] = W[((size_t)(gate * HH + jgrp * 4 + jl)) * HH + k];
    }
    for (int i = tid; i < 2 * HH * BB; i += 256) sm[16384 + i] = 0.0f;
    __syncthreads();

    float bias[4];
#pragma unroll
    for (int g = 0; g < 4; g++) bias[g] = bhh[g * HH + jgrp * 4 + fj];
    const int mylen = lengths[fb];
    const int jglob = jgrp * 4 + fj;

    const unsigned wbase = smem_u32(sm) + (unsigned)dir * 32768u + (unsigned)(kq * 128) * 64u + (unsigned)r2 * 8u;
    const unsigned hbase = smem_u32(sm) + 65536u + (unsigned)dir * 65536u + (unsigned)(kq * 128) * 128u + (unsigned)o * 16u;
    const unsigned pbase = smem_u32(sm) + 196608u + (unsigned)dir * 8192u;
    float* shd = sm + 16384 + dir * (HH * BB);
    float* part = sm + 49152;
    const int barid = 1 + dir;

    // prefetch pre-gates for t=0 (finalize role: jglob, fb)
    float cz[4];
    int cpos = (dir && 0 < mylen) ? (mylen - 1) : 0;
    {
        size_t pb = (((size_t)dir * TT + cpos) * G4) * BB + fb;
#pragma unroll
        for (int g = 0; g < 4; g++) cz[g] = __ldcs(&g_pre[pb + (size_t)(g * HH + jglob) * BB]);
    }

    float c = 0.0f;
    for (int t = 0; t < TT; t++) {
        // prefetch next-step pre-gates (independent of barrier)
        float nz[4] = {0.f, 0.f, 0.f, 0.f};
        int npos = 0;
        if (t + 1 < TT) {
            npos = t + 1;
            if (dir && (t + 1) < mylen) npos = mylen - 1 - (t + 1);
            size_t pb = (((size_t)dir * TT + npos) * G4) * BB + fb;
#pragma unroll
            for (int g = 0; g < 4; g++) nz[g] = __ldcs(&g_pre[pb + (size_t)(g * HH + jglob) * BB]);
        }

        if (t) {
            // one poll warp per half, nanosleep backoff
            if (w == dir * 4) {
                if (lane == 0) {
                    unsigned r;
                    for (;;) {
                        asm volatile("ld.acquire.gpu.global.u32 %0, [%1];"
                                     : "=r"(r) : "l"(&g_release[dir]) : "memory");
                        if (r >= (unsigned)t) break;
                        __nanosleep(64);
                    }
                }
                __syncwarp();
            }
            named_bar(barid);
            // copy h[t] (64 KB, own dir) from L2 into smem [k][b]
            const float4* src = (const float4*)&g_h[dir][t & 1][0];
            float4* dst = (float4*)shd;
#pragma unroll
            for (int q = 0; q < 32; q++) dst[ht + q * 128] = __ldcg(&src[ht + q * 128]);
            named_bar(barid);
        }

        // ---- MAC: this warp covers k in [kq*128, kq*128+128), all 16 rows, all 32 b ----
        unsigned long long a0[4] = {0, 0, 0, 0};   // row 2*r2:   b pairs (o*4), (o*4+2), (16+o*4), (16+o*4+2)
        unsigned long long a1[4] = {0, 0, 0, 0};   // row 2*r2+1
#pragma unroll 4
        for (int k = 0; k < 128; k++) {
            unsigned long long wp = lds_u64(wbase + (unsigned)k * 64u);   // (w_row0, w_row1)
            unsigned long long w00 = pack2((unsigned)wp);
            unsigned long long w11 = pack2((unsigned)(wp >> 32));
            unsigned long long hA, hB, hC, hD;
            lds_v2u64(hbase + (unsigned)k * 128u, hA, hB);        // b o*4..o*4+3
            lds_v2u64(hbase + (unsigned)k * 128u + 64u, hC, hD);  // b 16+o*4..
            fma2(a0[0], w00, hA); fma2(a0[1], w00, hB);
            fma2(a0[2], w00, hC); fma2(a0[3], w00, hD);
            fma2(a1[0], w11, hA); fma2(a1[1], w11, hB);
            fma2(a1[2], w11, hC); fma2(a1[3], w11, hD);
        }

        // store partials: part[dir][kq][row][b]
        {
            unsigned rowb0 = (unsigned)(kq * 16 + r2 * 2) * 128u;       // row 2*r2, *32 floats*4B
            unsigned rowb1 = rowb0 + 128u;
            unsigned off0 = (unsigned)o * 16u;          // b = o*4
            unsigned off1 = 256u + (unsigned)o * 16u;   // b = 16+o*4 (16 floats * 4B... 16*4=64? no: b offset 16 -> 16*4B = 64)
            // NOTE: b stride is 4B; b=16 -> +64 bytes
            off1 = 64u + (unsigned)o * 16u;
            sts_v2u64(pbase + rowb0 + off0, a0[0], a0[1]);
            sts_v2u64(pbase + rowb0 + off1, a0[2], a0[3]);
            sts_v2u64(pbase + rowb1 + off0, a1[0], a1[1]);
            sts_v2u64(pbase + rowb1 + off1, a1[2], a1[3]);
        }
        named_bar(barid);

        // ---- finalize: thread (fj, fb) of this half ----
        float z[4];
#pragma unroll
        for (int g = 0; g < 4; g++) {
            float s = cz[g] + bias[g];
#pragma unroll
            for (int q = 0; q < 4; q++)
                s += part[dir * 2048 + (q * 16 + g * 4 + fj) * 32 + fb];
            z[g] = s;
        }

        float gi = 1.0f / (1.0f + expf(-z[0]));
        float gf = 1.0f / (1.0f + expf(-z[1]));
        float gg = 1.0f - 2.0f / (expf(2.0f * z[2]) + 1.0f);
        float go = 1.0f / (1.0f + expf(-z[3]));

        c = gf * c + gi * gg;
        float h = go * (1.0f - 2.0f / (expf(2.0f * c) + 1.0f));

        g_h[dir][(t + 1) & 1][jglob * BB + fb] = h;
        g_lo2[(((size_t)dir * TT + cpos) * HH + jglob) * BB + fb] = h;

        if (t + 1 < TT) {
            named_bar(barid);   // all h stores of this half issued
            if (ht == 0) {
                unsigned old;
                asm volatile("atom.acq_rel.gpu.global.add.u32 %0, [%1], %2;"
                             : "=r"(old) : "l"(&g_arr1[dir][jgrp & 7]), "r"(1u) : "memory");
                if (old == (unsigned)(16 * (t + 1) - 1)) {
                    unsigned old2;
                    asm volatile("atom.acq_rel.gpu.global.add.u32 %0, [%1], %2;"
                                 : "=r"(old2) : "l"(&g_arr2[dir]), "r"(1u) : "memory");
                    if (old2 == (unsigned)(8 * (t + 1) - 1)) {
                        asm volatile("st.release.gpu.global.u32 [%0], %1;"
                                     :: "l"(&g_release[dir]), "r"((unsigned)(t + 1)) : "memory");
                    }
                }
            }
        }
#pragma unroll
        for (int g = 0; g < 4; g++) cz[g] = nz[g];
        cpos = npos;
    }
}

// ---------------- feats: per-t GEMM  out[k][b] = Wout[k][:] . h[:][b] ----------------
__global__ void __launch_bounds__(640) k_feats(
    const float* __restrict__ Wout, const float* __restrict__ bout)
{
    extern __shared__ float sm[];
    float* sW = sm;                 // [20][1024]
    float* sh = sm + 20480;         // [1024][32]
    __shared__ float sb[KK];
    int t = blockIdx.x;
    int tid = threadIdx.x, warp = tid >> 5, lane = tid & 31;

    for (int i = tid * 4; i < KK * 2 * HH; i += 2560)
        *(float4*)&sW[i] = *(const float4*)&Wout[i];
    for (int d = 0; d < 2; d++) {
        const float4* src = (const float4*)&g_lo2[(((size_t)d * TT + t) * HH) * BB];
        float4* dst = (float4*)&sh[d * HH * BB];
        for (int i = tid; i < HH * BB / 4; i += 640) dst[i] = src[i];
    }
    if (tid < KK) sb[tid] = bout[tid];
    __syncthreads();

    float acc = 0.0f;
    const float* wrow = &sW[warp * 2 * HH];
#pragma unroll 8
    for (int jj = 0; jj < 2 * HH; jj += 4) {
        float4 wv = *(const float4*)&wrow[jj];
        acc = fmaf(wv.x, sh[(jj + 0) * BB + lane], acc);
        acc = fmaf(wv.y, sh[(jj + 1) * BB + lane], acc);
        acc = fmaf(wv.z, sh[(jj + 2) * BB + lane], acc);
        acc = fmaf(wv.w, sh[(jj + 3) * BB + lane], acc);
    }
    g_feats[((size_t)lane * TT + t) * KK + warp] = acc + sb[warp];
}

// ---------------- Viterbi forward + backtrace, one warp per batch ----------------
__global__ void k_viterbi(const float* __restrict__ trans,
                          const int* __restrict__ lengths,
                          float* __restrict__ out)
{
    __shared__ unsigned char bp[TT][KK];
    int b = blockIdx.x;
    int nx = threadIdx.x;
    int len = lengths[b];

    float tr[KK];
#pragma unroll
    for (int p = 0; p < KK; p++) tr[p] = (nx < KK) ? trans[nx * KK + p] : 0.0f;

    float fv = (nx == START_TAG) ? 0.0f : NEGV;
    for (int t = 0; t < len; t++) {
        float best = -INFINITY; int barg = 0;
#pragma unroll
        for (int p = 0; p < KK; p++) {
            float fvp = __shfl_sync(0xffffffffu, fv, p);
            float s = fvp + tr[p];
            if (s > best) { best = s; barg = p; }
        }
        if (nx < KK) {
            bp[t][nx] = (unsigned char)barg;
            fv = best + g_feats[((size_t)b * TT + t) * KK + nx];
        } else {
            fv = NEGV;
        }
        __syncwarp();
    }

    float term = (nx < KK) ? (fv + trans[END_TAG * KK + nx]) : -INFINITY;
    float bestv = -INFINITY; int bt = 0;
#pragma unroll
    for (int p = 0; p < KK; p++) {
        float v = __shfl_sync(0xffffffffu, term, p);
        if (v > bestv) { bestv = v; bt = p; }
    }

    if (nx == 0) {
        out[b] = bestv;
        float* path = out + BB + (size_t)b * (TT + 1);
        path[TT] = (float)bt;
        int cur = bt;
        for (int i = 1; i <= len; i++) {
            cur = bp[len - i][cur];
            path[TT - i] = (float)cur;
        }
        for (int idx = 0; idx < TT - len; idx++) path[idx] = (float)KK;
    }
}

// ---------------- launch ----------------
extern "C" void kernel_launch(void* const* d_in, const int* in_sizes, int n_in,
                              void* d_out, int out_size) {
    const int*   sent  = (const int*)d_in[0];
    const int*   lens  = (const int*)d_in[1];
    const float* emb   = (const float*)d_in[2];
    const float* Wf_ih = (const float*)d_in[3];
    const float* Wf_hh = (const float*)d_in[4];
    const float* bf_ih = (const float*)d_in[5];
    const float* bf_hh = (const float*)d_in[6];
    const float* Wb_ih = (const float*)d_in[7];
    const float* Wb_hh = (const float*)d_in[8];
    const float* bb_ih = (const float*)d_in[9];
    const float* bb_hh = (const float*)d_in[10];
    const float* Wout  = (const float*)d_in[11];
    const float* bout  = (const float*)d_in[12];
    const float* trans = (const float*)d_in[13];
    float* out = (float*)d_out;

    const int smem_pregemm = (128 * 68 + 64 * 258) * 4;          // ~98.5 KB
    const int smem_lstm    = (16384 + 32768 + 4096) * 4;         // 212992 B ~208 KB
    const int smem_feats   = (KK * 2 * HH + 2 * HH * BB) * 4;    // 208 KB
    cudaFuncSetAttribute(k_pregemm, cudaFuncAttributeMaxDynamicSharedMemorySize, smem_pregemm);
    cudaFuncSetAttribute(k_lstm,    cudaFuncAttributeMaxDynamicSharedMemorySize, smem_lstm);
    cudaFuncSetAttribute(k_feats,   cudaFuncAttributeMaxDynamicSharedMemorySize, smem_feats);

    k_init<<<1, 32>>>();
    k_nop<<<1, 32>>>();   // launch-order shim: puts k_lstm in ncu's -s 5 window

    k_pregemm<<<dim3(TT, G4 / 64, 2), 256, smem_pregemm>>>(sent, emb, Wf_ih, Wb_ih, bf_ih, bb_ih);

    k_lstm<<<NBLK, 256, smem_lstm>>>(Wf_hh, Wb_hh, bf_hh, bb_hh, lens);

    k_feats<<<TT, 640, smem_feats>>>(Wout, bout);

    k_viterbi<<<BB, 32>>>(trans, lens, out);
}

// round 8
// speedup vs baseline: 1.1650x; 1.1086x over previous
#include <cuda_runtime.h>
#include <math.h>

#define BB 32
#define TT 256
#define EE 256
#define HH 512
#define G4 2048   // 4*HH
#define KK 20
#define START_TAG 18
#define END_TAG 19
#define NEGV (-10000.0f)
#define NBLK 128

// ---------------- device-global scratch ----------------
__device__ float g_pre[(size_t)2 * TT * G4 * BB];              // [dir][t][gate][b]
__device__ __align__(16) float2 g_hp[2][2][256 * BB];          // [dir][buf][pair*BB+b]
__device__ float g_lo2[(size_t)2 * TT * HH * BB];              // [dir][t][j][b]
__device__ float g_feats[(size_t)BB * TT * KK];                // [b][t][k]
__device__ unsigned g_arrive[2];

// ---------------- helpers ----------------
__device__ __forceinline__ unsigned smem_u32(const void* p) {
    unsigned a;
    asm("{ .reg .u64 t; cvta.to.shared.u64 t, %1; cvt.u32.u64 %0, t; }" : "=r"(a) : "l"(p));
    return a;
}
__device__ __forceinline__ void fma2(unsigned long long& acc, unsigned long long a, unsigned long long b) {
    asm("fma.rn.f32x2 %0, %1, %2, %0;" : "+l"(acc) : "l"(a), "l"(b));
}
__device__ __forceinline__ void lds_v2u64(unsigned addr, unsigned long long& a, unsigned long long& b) {
    asm("ld.shared.v2.u64 {%0,%1}, [%2];" : "=l"(a), "=l"(b) : "r"(addr));
}
__device__ __forceinline__ unsigned long long lds_u64(unsigned addr) {
    unsigned long long v;
    asm("ld.shared.u64 %0, [%1];" : "=l"(v) : "r"(addr));
    return v;
}
__device__ __forceinline__ float hsum2(unsigned long long a) {
    return __uint_as_float((unsigned)a) + __uint_as_float((unsigned)(a >> 32));
}
__device__ __forceinline__ void named_bar(int id) {
    asm volatile("bar.sync %0, 128;" :: "r"(id) : "memory");
}
__device__ __forceinline__ void mbar_wait(unsigned addr, unsigned parity) {
    unsigned done;
    do {
        asm volatile(
            "{ .reg .pred p;\n\t"
            "mbarrier.try_wait.parity.acquire.cta.shared::cta.b64 p, [%1], %2, 0x989680;\n\t"
            "selp.b32 %0, 1, 0, p; }"
            : "=r"(done) : "r"(addr), "r"(parity) : "memory");
    } while (!done);
}

// ---------------- init: reset barrier state (inside graph, every replay) ----------------
__global__ void k_init() {
    if (threadIdx.x < 2) g_arrive[threadIdx.x] = 0u;
}

// no-op: launch-order shim so ncu's -s 5 window lands on k_lstm
__global__ void k_nop() {}

// ---------------- input-projection GEMM (f32x2), embedding gather fused ----------------
__global__ void __launch_bounds__(256) k_pregemm(
    const int* __restrict__ sent, const float* __restrict__ emb,
    const float* __restrict__ Wf, const float* __restrict__ Wb,
    const float* __restrict__ bf, const float* __restrict__ bb)
{
    extern __shared__ float sm[];
    float* xsf = sm;               // x pairs: [ep][b][2], stride 68 floats/ep
    float* wsf = sm + 128 * 68;    // w rows:  [r][e], stride 258 floats/row
    __shared__ int stok[BB];

    int t = blockIdx.x, gc = blockIdx.y, dir = blockIdx.z;
    int tid = threadIdx.x;
    if (tid < BB) stok[tid] = sent[tid * TT + t];
    __syncthreads();

    const float* W  = dir ? Wb : Wf;
    const float* bi = dir ? bb : bf;

    for (int i = tid; i < BB * EE; i += 256) {
        int b = i >> 8, e = i & 255;
        xsf[(e >> 1) * 68 + b * 2 + (e & 1)] = emb[(size_t)stok[b] * EE + e];
    }
    int g0blk = gc * 64;
    for (int i = tid; i < 64 * EE; i += 256) {
        int r = i >> 8, e = i & 255;
        wsf[r * 258 + e] = W[(size_t)(g0blk + r) * EE + e];
    }
    __syncthreads();

    int tx = tid & 15, ty = tid >> 4;
    int b0 = tx * 2;
    int g0 = ty * 4;
    unsigned xb = smem_u32(xsf) + (unsigned)b0 * 8u;
    unsigned wb = smem_u32(wsf) + (unsigned)g0 * 1032u;

    unsigned long long a[4][2];
#pragma unroll
    for (int q = 0; q < 4; q++) { a[q][0] = 0ull; a[q][1] = 0ull; }

#pragma unroll 4
    for (int ep = 0; ep < 128; ep++) {
        unsigned long long x0, x1;
        lds_v2u64(xb + (unsigned)ep * 272u, x0, x1);
        unsigned long long w0 = lds_u64(wb + (unsigned)ep * 8u);
        unsigned long long w1 = lds_u64(wb + 1032u + (unsigned)ep * 8u);
        unsigned long long w2 = lds_u64(wb + 2064u + (unsigned)ep * 8u);
        unsigned long long w3 = lds_u64(wb + 3096u + (unsigned)ep * 8u);
        fma2(a[0][0], w0, x0); fma2(a[0][1], w0, x1);
        fma2(a[1][0], w1, x0); fma2(a[1][1], w1, x1);
        fma2(a[2][0], w2, x0); fma2(a[2][1], w2, x1);
        fma2(a[3][0], w3, x0); fma2(a[3][1], w3, x1);
    }

    size_t base = (((size_t)dir * TT + t) * G4 + g0blk) * BB;
#pragma unroll
    for (int q = 0; q < 4; q++) {
        int g = g0 + q;
        float bv = bi[g0blk + g];
        float2 st = make_float2(hsum2(a[q][0]) + bv, hsum2(a[q][1]) + bv);
        *(float2*)&g_pre[base + (size_t)g * BB + b0] = st;
    }
}

// ---------------- persistent BiLSTM recurrence (R5 body + bulk-copy exchange) ----------------
// 128 blocks x 256 threads. warp w: dir=w>>2, p=(w>>1)&1 (j-pair), kh=w&1 (k-half).
// h exchange: cp.async.bulk from L2 + smem mbarrier; arrive via red.release; pollers
// read the arrive counter directly (threshold NBLK*t).
__global__ void __launch_bounds__(256, 1) k_lstm(
    const float* __restrict__ Wfhh, const float* __restrict__ Wbhh,
    const float* __restrict__ bfhh, const float* __restrict__ bbhh,
    const int* __restrict__ lengths)
{
    extern __shared__ float sm[];
    // floats: [0,16384) interleaved weights; [16384,49152) h; [49152,50176) partials;
    // bytes 200704..200720: two mbarriers
    const int jgrp = (int)blockIdx.x;
    const int tid = threadIdx.x;
    const int w = tid >> 5, lane = tid & 31;
    const int dir = w >> 2, p = (w >> 1) & 1, kh = w & 1;
    const int jown = jgrp * 4 + p * 2 + kh;
    const unsigned mbar = smem_u32(sm) + 200704u + (unsigned)dir * 8u;

    // one-time: interleaved weight load
    for (int idx = tid; idx < 16384; idx += 256) {
        int ww = idx >> 11;
        int r = idx & 2047;
        int kq = r >> 4, c = r & 15;
        int jj = c >> 3, gate = (c >> 1) & 3, kk = c & 1;
        int d = ww >> 2, pp = (ww >> 1) & 1, kk2 = ww & 1;
        const float* W = d ? Wbhh : Wfhh;
        int jr = jgrp * 4 + pp * 2 + jj;
        int k = kk2 * 256 + kq * 2 + kk;
        sm[idx] = W[((size_t)(gate * HH + jr)) * HH + k];
    }
    for (int i = tid; i < 2 * HH * BB; i += 256) sm[16384 + i] = 0.0f;
    if (tid == 0) {
        asm volatile("mbarrier.init.shared.b64 [%0], 1;" :: "r"(mbar) : "memory");
        asm volatile("mbarrier.init.shared.b64 [%0], 1;" :: "r"(mbar + 8u) : "memory");
    }
    __syncthreads();

    const float* bhh = dir ? bbhh : bfhh;
    float bg[4];
#pragma unroll
    for (int g = 0; g < 4; g++) bg[g] = bhh[g * HH + jown];
    const int mylen = lengths[lane];

    const unsigned smWb = smem_u32(sm) + (unsigned)w * 8192u;
    const unsigned smh  = smem_u32(sm) + 65536u + (unsigned)dir * 65536u + (unsigned)kh * 32768u + (unsigned)lane * 8u;
    const unsigned hdst = smem_u32(sm) + 65536u + (unsigned)dir * 65536u;
    float* part = sm + 49152;
    const int barid = 1 + dir;

    // prefetch pre-gates for t=0
    float cz[4];
    int cpos = (dir && 0 < mylen) ? (mylen - 1) : 0;
    {
        size_t pb = (((size_t)dir * TT + cpos) * G4) * BB + lane;
#pragma unroll
        for (int g = 0; g < 4; g++) cz[g] = __ldcs(&g_pre[pb + (size_t)(g * HH + jown) * BB]);
    }

    float c = 0.0f;
    for (int t = 0; t < TT; t++) {
        // prefetch next-step pre-gates (independent of barrier / h)
        float nz[4] = {0.f, 0.f, 0.f, 0.f};
        int npos = 0;
        if (t + 1 < TT) {
            npos = t + 1;
            if (dir && (t + 1) < mylen) npos = mylen - 1 - (t + 1);
            size_t pb = (((size_t)dir * TT + npos) * G4) * BB + lane;
#pragma unroll
            for (int g = 0; g < 4; g++) nz[g] = __ldcs(&g_pre[pb + (size_t)(g * HH + jown) * BB]);
        }

        if (t) {
            // poll thread per half, then one bulk copy; everyone sleeps on the mbarrier
            if (tid == dir * 128) {
                unsigned need = (unsigned)(NBLK * t);
                unsigned r;
                for (;;) {
                    asm volatile("ld.acquire.gpu.global.u32 %0, [%1];"
                                 : "=r"(r) : "l"(&g_arrive[dir]) : "memory");
                    if (r >= need) break;
                    __nanosleep(64);
                }
                asm volatile("fence.proxy.async;" ::: "memory");
                asm volatile("mbarrier.arrive.expect_tx.shared.b64 _, [%0], %1;"
                             :: "r"(mbar), "r"(65536u) : "memory");
                asm volatile("cp.async.bulk.shared::cluster.global.mbarrier::complete_tx::bytes [%0], [%1], %2, [%3];"
                             :: "r"(hdst), "l"((const void*)&g_hp[dir][t & 1][0]), "r"(65536u), "r"(mbar)
                             : "memory");
            }
            mbar_wait(mbar, (unsigned)((t - 1) & 1));
        }

        // ---- MAC over this warp's k-half for both j's of the pair ----
        unsigned long long ai0 = 0, af0 = 0, ag0 = 0, ao0 = 0;
        unsigned long long ai1 = 0, af1 = 0, ag1 = 0, ao1 = 0;
#pragma unroll 4
        for (int kq = 0; kq < 128; kq++) {
            unsigned wa = smWb + (unsigned)kq * 64u;
            unsigned long long wi0, wf0, wg0, wo0, wi1, wf1, wg1, wo1;
            lds_v2u64(wa,       wi0, wf0);
            lds_v2u64(wa + 16u, wg0, wo0);
            lds_v2u64(wa + 32u, wi1, wf1);
            lds_v2u64(wa + 48u, wg1, wo1);
            unsigned long long h2 = lds_u64(smh + (unsigned)kq * 256u);
            fma2(ai0, wi0, h2); fma2(af0, wf0, h2); fma2(ag0, wg0, h2); fma2(ao0, wo0, h2);
            fma2(ai1, wi1, h2); fma2(af1, wf1, h2); fma2(ag1, wg1, h2); fma2(ao1, wo1, h2);
        }

        // partner partials: the j this warp does NOT own (jj = 1-kh)
        float po[4], pn[4];
        if (kh == 0) { pn[0] = hsum2(ai1); pn[1] = hsum2(af1); pn[2] = hsum2(ag1); pn[3] = hsum2(ao1);
                       po[0] = hsum2(ai0); po[1] = hsum2(af0); po[2] = hsum2(ag0); po[3] = hsum2(ao0); }
        else         { pn[0] = hsum2(ai0); pn[1] = hsum2(af0); pn[2] = hsum2(ag0); pn[3] = hsum2(ao0);
                       po[0] = hsum2(ai1); po[1] = hsum2(af1); po[2] = hsum2(ag1); po[3] = hsum2(ao1); }
#pragma unroll
        for (int g = 0; g < 4; g++) part[(w * 4 + g) * 32 + lane] = pn[g];
        named_bar(barid);

        float z[4];
#pragma unroll
        for (int g = 0; g < 4; g++)
            z[g] = cz[g] + bg[g] + po[g] + part[((w ^ 1) * 4 + g) * 32 + lane];

        float gi = 1.0f / (1.0f + expf(-z[0]));
        float gf = 1.0f / (1.0f + expf(-z[1]));
        float gg = 1.0f - 2.0f / (expf(2.0f * z[2]) + 1.0f);
        float go = 1.0f / (1.0f + expf(-z[3]));

        c = gf * c + gi * gg;
        float h = go * (1.0f - 2.0f / (expf(2.0f * c) + 1.0f));

        int pairIdx = jgrp * 2 + p;
        ((float*)&g_hp[dir][(t + 1) & 1][pairIdx * BB])[lane * 2 + kh] = h;
        g_lo2[(((size_t)dir * TT + cpos) * HH + jown) * BB + lane] = h;

        if (t + 1 < TT) {
            named_bar(barid);   // all 4 warps of this half stored h
            if (tid == dir * 128) {
                asm volatile("red.release.gpu.global.add.u32 [%0], %1;"
                             :: "l"(&g_arrive[dir]), "r"(1u) : "memory");
            }
        }
#pragma unroll
        for (int g = 0; g < 4; g++) cz[g] = nz[g];
        cpos = npos;
    }
}

// ---------------- feats: per-t GEMM  out[k][b] = Wout[k][:] . h[:][b] ----------------
__global__ void __launch_bounds__(640) k_feats(
    const float* __restrict__ Wout, const float* __restrict__ bout)
{
    extern __shared__ float sm[];
    float* sW = sm;                 // [20][1024]
    float* sh = sm + 20480;         // [1024][32]
    __shared__ float sb[KK];
    int t = blockIdx.x;
    int tid = threadIdx.x, warp = tid >> 5, lane = tid & 31;

    for (int i = tid * 4; i < KK * 2 * HH; i += 2560)
        *(float4*)&sW[i] = *(const float4*)&Wout[i];
    for (int d = 0; d < 2; d++) {
        const float4* src = (const float4*)&g_lo2[(((size_t)d * TT + t) * HH) * BB];
        float4* dst = (float4*)&sh[d * HH * BB];
        for (int i = tid; i < HH * BB / 4; i += 640) dst[i] = src[i];
    }
    if (tid < KK) sb[tid] = bout[tid];
    __syncthreads();

    float acc = 0.0f;
    const float* wrow = &sW[warp * 2 * HH];
#pragma unroll 8
    for (int jj = 0; jj < 2 * HH; jj += 4) {
        float4 wv = *(const float4*)&wrow[jj];
        acc = fmaf(wv.x, sh[(jj + 0) * BB + lane], acc);
        acc = fmaf(wv.y, sh[(jj + 1) * BB + lane], acc);
        acc = fmaf(wv.z, sh[(jj + 2) * BB + lane], acc);
        acc = fmaf(wv.w, sh[(jj + 3) * BB + lane], acc);
    }
    g_feats[((size_t)lane * TT + t) * KK + warp] = acc + sb[warp];
}

// ---------------- Viterbi forward + backtrace, one warp per batch ----------------
__global__ void k_viterbi(const float* __restrict__ trans,
                          const int* __restrict__ lengths,
                          float* __restrict__ out)
{
    __shared__ unsigned char bp[TT][KK];
    int b = blockIdx.x;
    int nx = threadIdx.x;
    int len = lengths[b];

    float tr[KK];
#pragma unroll
    for (int p = 0; p < KK; p++) tr[p] = (nx < KK) ? trans[nx * KK + p] : 0.0f;

    float fv = (nx == START_TAG) ? 0.0f : NEGV;
    for (int t = 0; t < len; t++) {
        float best = -INFINITY; int barg = 0;
#pragma unroll
        for (int p = 0; p < KK; p++) {
            float fvp = __shfl_sync(0xffffffffu, fv, p);
            float s = fvp + tr[p];
            if (s > best) { best = s; barg = p; }
        }
        if (nx < KK) {
            bp[t][nx] = (unsigned char)barg;
            fv = best + g_feats[((size_t)b * TT + t) * KK + nx];
        } else {
            fv = NEGV;
        }
        __syncwarp();
    }

    float term = (nx < KK) ? (fv + trans[END_TAG * KK + nx]) : -INFINITY;
    float bestv = -INFINITY; int bt = 0;
#pragma unroll
    for (int p = 0; p < KK; p++) {
        float v = __shfl_sync(0xffffffffu, term, p);
        if (v > bestv) { bestv = v; bt = p; }
    }

    if (nx == 0) {
        out[b] = bestv;
        float* path = out + BB + (size_t)b * (TT + 1);
        path[TT] = (float)bt;
        int cur = bt;
        for (int i = 1; i <= len; i++) {
            cur = bp[len - i][cur];
            path[TT - i] = (float)cur;
        }
        for (int idx = 0; idx < TT - len; idx++) path[idx] = (float)KK;
    }
}

// ---------------- launch ----------------
extern "C" void kernel_launch(void* const* d_in, const int* in_sizes, int n_in,
                              void* d_out, int out_size) {
    const int*   sent  = (const int*)d_in[0];
    const int*   lens  = (const int*)d_in[1];
    const float* emb   = (const float*)d_in[2];
    const float* Wf_ih = (const float*)d_in[3];
    const float* Wf_hh = (const float*)d_in[4];
    const float* bf_ih = (const float*)d_in[5];
    const float* bf_hh = (const float*)d_in[6];
    const float* Wb_ih = (const float*)d_in[7];
    const float* Wb_hh = (const float*)d_in[8];
    const float* bb_ih = (const float*)d_in[9];
    const float* bb_hh = (const float*)d_in[10];
    const float* Wout  = (const float*)d_in[11];
    const float* bout  = (const float*)d_in[12];
    const float* trans = (const float*)d_in[13];
    float* out = (float*)d_out;

    const int smem_pregemm = (128 * 68 + 64 * 258) * 4;          // ~98.5 KB
    const int smem_lstm    = 200704 + 16;                         // weights+h+part+mbarriers
    const int smem_feats   = (KK * 2 * HH + 2 * HH * BB) * 4;    // 208 KB
    cudaFuncSetAttribute(k_pregemm, cudaFuncAttributeMaxDynamicSharedMemorySize, smem_pregemm);
    cudaFuncSetAttribute(k_lstm,    cudaFuncAttributeMaxDynamicSharedMemorySize, smem_lstm);
    cudaFuncSetAttribute(k_feats,   cudaFuncAttributeMaxDynamicSharedMemorySize, smem_feats);

    k_init<<<1, 32>>>();
    k_nop<<<1, 32>>>();   // keep launch order identical (ncu window on k_lstm)

    k_pregemm<<<dim3(TT, G4 / 64, 2), 256, smem_pregemm>>>(sent, emb, Wf_ih, Wb_ih, bf_ih, bb_ih);

    k_lstm<<<NBLK, 256, smem_lstm>>>(Wf_hh, Wb_hh, bf_hh, bb_hh, lens);

    k_feats<<<TT, 640, smem_feats>>>(Wout, bout);

    k_viterbi<<<BB, 32>>>(trans, lens, out);
}